// round 4
// baseline (speedup 1.0000x reference)
#include <cuda_runtime.h>
#include <cuda_fp16.h>
#include <cstdint>

// ---------------------------------------------------------------------------
// out[b,o,hw] = sum_c W[o,c] * relu(x[b,c,hw]*scale[c]+shift[c])
// GEMM M=12544 (b*49+hw), N=192, K=2112. fp16 mma.sync m16n8k16, fp32 accum.
// Pipeline: B via cp.async fp16 (4-stage), A via 2-deep register prefetch
// (LDG fp32 -> BN+ReLU -> cvt fp16 -> STS), fragments via ldmatrix.x4.
// ---------------------------------------------------------------------------
constexpr int CIN   = 2112;
constexpr int COUT  = 192;
constexpr int HWSZ  = 49;
constexpr int M_TOTAL = 256 * HWSZ;   // 12544
constexpr int BM = 128;
constexpr int BK = 32;
constexpr int NKT = CIN / BK;         // 66
constexpr int GRID_M = M_TOTAL / BM;  // 98

// smem: padded rows, 40 halves (80 B) per 32-k row -> conflict-free STS & LDSM
constexpr int STRIDE  = 80;                    // bytes
constexpr int A_STAGE = BM * STRIDE;           // 10240
constexpr int B_STAGE = COUT * STRIDE;         // 15360
constexpr int SMEM_A0 = 0;                     // 2 stages
constexpr int SMEM_B0 = 2 * A_STAGE;           // 20480, 4 stages
constexpr int SMEM_TOTAL = SMEM_B0 + 4 * B_STAGE;  // 81920

__device__ __align__(16) float  g_scale[CIN];
__device__ __align__(16) float  g_shift[CIN];
__device__ __align__(16) __half g_W16[COUT * CIN];   // fp16 copy of W

__device__ __forceinline__ uint32_t smem_u32(const void* p) {
    uint32_t a;
    asm("{ .reg .u64 t; cvta.to.shared.u64 t, %1; cvt.u32.u64 %0, t; }" : "=r"(a) : "l"(p));
    return a;
}
__device__ __forceinline__ uint32_t pack_h2(float lo, float hi) {
    __half2 h = __floats2half2_rn(lo, hi);
    return *reinterpret_cast<uint32_t*>(&h);
}
__device__ __forceinline__ void cp_async16(uint32_t saddr, const void* g) {
    asm volatile("cp.async.cg.shared.global [%0], [%1], 16;" :: "r"(saddr), "l"(g));
}
__device__ __forceinline__ void cp_commit() {
    asm volatile("cp.async.commit_group;");
}
__device__ __forceinline__ void cp_wait3() {
    asm volatile("cp.async.wait_group 3;");
}
__device__ __forceinline__ void ldsm_x4(uint32_t* r, uint32_t addr) {
    asm volatile("ldmatrix.sync.aligned.m8n8.x4.shared.b16 {%0,%1,%2,%3}, [%4];"
                 : "=r"(r[0]), "=r"(r[1]), "=r"(r[2]), "=r"(r[3]) : "r"(addr));
}
__device__ __forceinline__ void mma16816(float& c0, float& c1, float& c2, float& c3,
                                         uint32_t a0, uint32_t a1, uint32_t a2, uint32_t a3,
                                         uint32_t b0, uint32_t b1) {
    asm volatile(
        "mma.sync.aligned.m16n8k16.row.col.f32.f16.f16.f32 "
        "{%0,%1,%2,%3}, {%4,%5,%6,%7}, {%8,%9}, {%0,%1,%2,%3};"
        : "+f"(c0), "+f"(c1), "+f"(c2), "+f"(c3)
        : "r"(a0), "r"(a1), "r"(a2), "r"(a3), "r"(b0), "r"(b1));
}

// ---------------------------------------------------------------------------
__global__ void prep_kernel(const float* __restrict__ gamma, const float* __restrict__ beta,
                            const float* __restrict__ mean,  const float* __restrict__ var) {
    int i = blockIdx.x * blockDim.x + threadIdx.x;
    if (i < CIN) {
        float inv = rsqrtf(var[i] + 1e-5f);
        float s = gamma[i] * inv;
        g_scale[i] = s;
        g_shift[i] = fmaf(-mean[i], s, beta[i]);
    }
}
__global__ void w16_kernel(const float* __restrict__ W) {
    int i = blockIdx.x * blockDim.x + threadIdx.x;
    if (i < COUT * CIN) g_W16[i] = __float2half_rn(W[i]);
}

// ---------------------------------------------------------------------------
// 256 threads = 8 warps as 2(M) x 4(N); warp tile 64 x 48.
// ---------------------------------------------------------------------------
__global__ void __launch_bounds__(256, 1)
gemm_kernel(const float* __restrict__ x, float* __restrict__ out) {
    extern __shared__ char smem[];
    const uint32_t sb = smem_u32(smem);
    const int tid = threadIdx.x;
    const int l = tid & 31;
    const int w = tid >> 5;
    const int m0 = blockIdx.x * BM;

    // ---- A loader: thread covers rows {rA, rA+64} x k-pairs {2(kb+4j)}
    const int kb = l >> 3;                 // 0..3
    const int rA = (l & 7) + (w << 3);     // 0..63
    int xbase0, xbase1;
    {
        int m = m0 + rA;        int b = m / HWSZ; xbase0 = b * (CIN * HWSZ) + (m - b * HWSZ);
        m = m0 + rA + 64;       b = m / HWSZ;     xbase1 = b * (CIN * HWSZ) + (m - b * HWSZ);
    }

    // ---- mma / fragment mapping
    const int g = l >> 2, t = l & 3;
    const int wm = (w >> 2) * 64;          // warp M offset
    const int wn = (w & 3) * 48;           // warp N offset
    // A ldmatrix lane address component
    const int rAf  = (l & 7) + (((l >> 3) & 1) << 3);   // row within 16
    const int cAf  = (l >> 4) * 16;                     // 16B col select
    const uint32_t aFragBase = (uint32_t)((wm + rAf) * STRIDE + cAf);
    // B ldmatrix lane address component (x4 covers 2 n-tiles)
    const int rBf  = (l & 7) + ((l >> 4) << 3);
    const int cBf  = ((l >> 3) & 1) * 16;
    const uint32_t bFragBase = (uint32_t)((wn + rBf) * STRIDE + cBf);

    float acc[4][6][4];
#pragma unroll
    for (int mt = 0; mt < 4; mt++)
#pragma unroll
        for (int nt = 0; nt < 6; nt++)
#pragma unroll
            for (int c = 0; c < 4; c++) acc[mt][nt][c] = 0.0f;

    float ar[2][16];   // two in-flight A register tiles

    auto ldgA = [&](int kt, float* a) {
        const int kk = kt * BK;
#pragma unroll
        for (int j = 0; j < 4; j++) {
            const int c0 = kk + (kb + 4 * j) * 2;
            const float* p0 = x + xbase0 + c0 * HWSZ;
            const float* p1 = x + xbase1 + c0 * HWSZ;
            a[j * 4 + 0] = p0[0]; a[j * 4 + 1] = p0[HWSZ];
            a[j * 4 + 2] = p1[0]; a[j * 4 + 3] = p1[HWSZ];
        }
    };
    auto stsA = [&](int kt, const float* a) {
        char* As = smem + SMEM_A0 + (kt & 1) * A_STAGE;
        const int kk = kt * BK;
#pragma unroll
        for (int j = 0; j < 4; j++) {
            const int c0 = kk + (kb + 4 * j) * 2;
            const float2 sc = *reinterpret_cast<const float2*>(g_scale + c0);
            const float2 sh = *reinterpret_cast<const float2*>(g_shift + c0);
            uint32_t v0 = pack_h2(fmaxf(fmaf(a[j * 4 + 0], sc.x, sh.x), 0.0f),
                                  fmaxf(fmaf(a[j * 4 + 1], sc.y, sh.y), 0.0f));
            uint32_t v1 = pack_h2(fmaxf(fmaf(a[j * 4 + 2], sc.x, sh.x), 0.0f),
                                  fmaxf(fmaf(a[j * 4 + 3], sc.y, sh.y), 0.0f));
            *reinterpret_cast<uint32_t*>(As + rA * STRIDE + (kb + 4 * j) * 4)        = v0;
            *reinterpret_cast<uint32_t*>(As + (rA + 64) * STRIDE + (kb + 4 * j) * 4) = v1;
        }
    };
    auto cpB = [&](int kt) {
        const uint32_t bs = sb + SMEM_B0 + (kt & 3) * B_STAGE;
        const __half* wsrc = g_W16 + kt * BK;
#pragma unroll
        for (int i = 0; i < 3; i++) {
            const int c = tid + 256 * i;         // 0..767
            const int row = c >> 2, j = c & 3;   // 192 rows x 4 x 16B
            cp_async16(bs + row * STRIDE + j * 16, wsrc + row * CIN + j * 8);
        }
    };

    // ---- prologue
    ldgA(0, ar[0]);
    ldgA(1, ar[1]);
    cpB(0); cp_commit();
    cpB(1); cp_commit();
    cpB(2); cp_commit();
    stsA(0, ar[0]);

#pragma unroll 1
    for (int kt = 0; kt < NKT; kt++) {
        if (kt + 3 < NKT) cpB(kt + 3);
        cp_commit();
        if (kt + 2 < NKT) ldgA(kt + 2, ar[kt & 1]);
        cp_wait3();
        __syncthreads();

        const uint32_t sA = sb + SMEM_A0 + (kt & 1) * A_STAGE;
        const uint32_t sB = sb + SMEM_B0 + (kt & 3) * B_STAGE;
#pragma unroll
        for (int s = 0; s < 2; s++) {
            uint32_t af[4][4], bf[3][4];
#pragma unroll
            for (int mt = 0; mt < 4; mt++)
                ldsm_x4(af[mt], sA + aFragBase + mt * 16 * STRIDE + s * 32);
#pragma unroll
            for (int p = 0; p < 3; p++)
                ldsm_x4(bf[p], sB + bFragBase + p * 16 * STRIDE + s * 32);
#pragma unroll
            for (int mt = 0; mt < 4; mt++)
#pragma unroll
                for (int p = 0; p < 3; p++) {
                    mma16816(acc[mt][2 * p][0], acc[mt][2 * p][1],
                             acc[mt][2 * p][2], acc[mt][2 * p][3],
                             af[mt][0], af[mt][1], af[mt][2], af[mt][3],
                             bf[p][0], bf[p][1]);
                    mma16816(acc[mt][2 * p + 1][0], acc[mt][2 * p + 1][1],
                             acc[mt][2 * p + 1][2], acc[mt][2 * p + 1][3],
                             af[mt][0], af[mt][1], af[mt][2], af[mt][3],
                             bf[p][2], bf[p][3]);
                }
        }

        if (kt + 1 < NKT) stsA(kt + 1, ar[(kt + 1) & 1]);
    }

    // ---- epilogue: c0,c1 = row g cols 2t,2t+1 ; c2,c3 = row g+8
#pragma unroll
    for (int mt = 0; mt < 4; mt++) {
#pragma unroll
        for (int h = 0; h < 2; h++) {
            const int m = m0 + wm + mt * 16 + g + 8 * h;
            const int b = m / HWSZ, hw = m - b * HWSZ;
            float* op = out + b * (COUT * HWSZ) + hw;
#pragma unroll
            for (int nt = 0; nt < 6; nt++) {
                const int n = wn + nt * 8 + 2 * t;
                op[n * HWSZ]       = acc[mt][nt][2 * h + 0];
                op[(n + 1) * HWSZ] = acc[mt][nt][2 * h + 1];
            }
        }
    }
}

// ---------------------------------------------------------------------------
extern "C" void kernel_launch(void* const* d_in, const int* in_sizes, int n_in,
                              void* d_out, int out_size) {
    (void)in_sizes; (void)n_in; (void)out_size;
    const float* x     = (const float*)d_in[0];
    const float* gamma = (const float*)d_in[1];
    const float* beta  = (const float*)d_in[2];
    const float* rmean = (const float*)d_in[3];
    const float* rvar  = (const float*)d_in[4];
    const float* W     = (const float*)d_in[5];
    float* out = (float*)d_out;

    cudaFuncSetAttribute(gemm_kernel, cudaFuncAttributeMaxDynamicSharedMemorySize, SMEM_TOTAL);

    prep_kernel<<<(CIN + 255) / 256, 256>>>(gamma, beta, rmean, rvar);
    w16_kernel<<<(COUT * CIN + 255) / 256, 256>>>(W);
    gemm_kernel<<<GRID_M, 256, SMEM_TOTAL>>>(x, out);
}

// round 5
// speedup vs baseline: 1.6435x; 1.6435x over previous
#include <cuda_runtime.h>
#include <cuda_fp16.h>
#include <cstdint>

// ---------------------------------------------------------------------------
// out[b,o,hw] = sum_c W[o,c] * relu(x[b,c,hw]*scale[c]+shift[c])
// Pass 1 (fuse): h[m,k] = fp16(relu(BN(x))) with m=b*49+hw, k=c (K-contiguous),
//                plus W -> fp16. Transpose via smem, fully coalesced both sides.
// Pass 2 (gemm): fp16 mma.sync m16n8k16, cp.async 4-stage pipeline for A and B.
// ---------------------------------------------------------------------------
constexpr int CIN   = 2112;
constexpr int COUT  = 192;
constexpr int HWSZ  = 49;
constexpr int M_TOTAL = 256 * HWSZ;   // 12544
constexpr int BM = 64;
constexpr int BK = 32;
constexpr int NKT = CIN / BK;         // 66
constexpr int GRID_M = M_TOTAL / BM;  // 196

// gemm smem: padded rows (32 halves + 8 pad = 80 B) -> conflict-free LDSM
constexpr int STRIDE  = 80;
constexpr int A_STAGE = BM * STRIDE;            // 5120
constexpr int B_STAGE = COUT * STRIDE;          // 15360
constexpr int SMEM_B0 = 4 * A_STAGE;            // 20480
constexpr int SMEM_TOTAL = SMEM_B0 + 4 * B_STAGE;  // 81920

__device__ __align__(16) __half g_h16[M_TOTAL * CIN];  // 53 MB scratch
__device__ __align__(16) __half g_W16[COUT * CIN];

// fuse grid split
constexpr int CCH   = 64;                 // channels per transform CTA
constexpr int NCH   = CIN / CCH;          // 33
constexpr int NT_CTA = 256 * NCH;         // 8448 transform CTAs
constexpr int NW_CTA = (COUT * CIN) / 2048;  // 198 W-convert CTAs

__device__ __forceinline__ uint32_t smem_u32(const void* p) {
    uint32_t a;
    asm("{ .reg .u64 t; cvta.to.shared.u64 t, %1; cvt.u32.u64 %0, t; }" : "=r"(a) : "l"(p));
    return a;
}
__device__ __forceinline__ uint32_t pack_h2(float lo, float hi) {
    __half2 h = __floats2half2_rn(lo, hi);
    return *reinterpret_cast<uint32_t*>(&h);
}
__device__ __forceinline__ void cp_async16(uint32_t saddr, const void* g) {
    asm volatile("cp.async.cg.shared.global [%0], [%1], 16;" :: "r"(saddr), "l"(g));
}
__device__ __forceinline__ void cp_commit() { asm volatile("cp.async.commit_group;"); }
__device__ __forceinline__ void cp_wait3()  { asm volatile("cp.async.wait_group 3;"); }
__device__ __forceinline__ void ldsm_x4(uint32_t* r, uint32_t addr) {
    asm volatile("ldmatrix.sync.aligned.m8n8.x4.shared.b16 {%0,%1,%2,%3}, [%4];"
                 : "=r"(r[0]), "=r"(r[1]), "=r"(r[2]), "=r"(r[3]) : "r"(addr));
}
__device__ __forceinline__ void mma16816(float& c0, float& c1, float& c2, float& c3,
                                         uint32_t a0, uint32_t a1, uint32_t a2, uint32_t a3,
                                         uint32_t b0, uint32_t b1) {
    asm volatile(
        "mma.sync.aligned.m16n8k16.row.col.f32.f16.f16.f32 "
        "{%0,%1,%2,%3}, {%4,%5,%6,%7}, {%8,%9}, {%0,%1,%2,%3};"
        : "+f"(c0), "+f"(c1), "+f"(c2), "+f"(c3)
        : "r"(a0), "r"(a1), "r"(a2), "r"(a3), "r"(b0), "r"(b1));
}

// ---------------------------------------------------------------------------
// Pass 1: BN+ReLU+fp16 transpose of x, and W -> fp16.
// Transform CTA: one (b, 64-channel chunk); smem tile [64][51] floats.
// ---------------------------------------------------------------------------
__global__ void __launch_bounds__(256)
fuse_kernel(const float* __restrict__ x,
            const float* __restrict__ gamma, const float* __restrict__ beta,
            const float* __restrict__ mean,  const float* __restrict__ var,
            const float* __restrict__ W) {
    const int tid = threadIdx.x;
    const int bid = blockIdx.x;

    if (bid >= NT_CTA) {   // ---- W conversion
        const int base = (bid - NT_CTA) * 2048 + tid;
#pragma unroll
        for (int i = 0; i < 8; i++) {
            const int idx = base + 256 * i;
            g_W16[idx] = __float2half_rn(W[idx]);
        }
        return;
    }

    __shared__ float smf[CCH * 51];        // row stride 51 floats
    __shared__ float ssc[CCH], ssh[CCH];

    const int b  = bid / NCH;
    const int c0 = (bid - b * NCH) * CCH;

    if (tid < CCH) {
        const int c = c0 + tid;
        float inv = rsqrtf(var[c] + 1e-5f);
        float s = gamma[c] * inv;
        ssc[tid] = s;
        ssh[tid] = fmaf(-mean[c], s, beta[c]);
    }
    __syncthreads();

    // read 64x49 floats contiguous, BN+ReLU, store to padded smem
    const float* src = x + (b * CIN + c0) * HWSZ;
#pragma unroll
    for (int i = 0; i < 13; i++) {
        const int idx = tid + 256 * i;     // c*49 + hw
        if (idx < CCH * HWSZ) {
            const int c = (unsigned)idx / HWSZ;
            float v = fmaxf(fmaf(src[idx], ssc[c], ssh[c]), 0.0f);
            smf[idx + 2 * c] = v;          // c*51 + hw == idx + 2c
        }
    }
    __syncthreads();

    // write transposed: h[(b*49+hw)*2112 + c0 + 2cp .. +1] as half2
#pragma unroll
    for (int i = 0; i < 7; i++) {
        const int j = tid + 256 * i;       // hw*32 + cpair
        if (j < HWSZ * (CCH / 2)) {
            const int hw = j >> 5, cp = j & 31;
            float v0 = smf[(2 * cp) * 51 + hw];
            float v1 = smf[(2 * cp + 1) * 51 + hw];
            *reinterpret_cast<uint32_t*>(g_h16 + (size_t)(b * HWSZ + hw) * CIN + c0 + 2 * cp)
                = pack_h2(v0, v1);
        }
    }
}

// ---------------------------------------------------------------------------
// Pass 2: GEMM. 128 threads = 4 warps (warp tile 64 x 48), 2 CTAs/SM.
// ---------------------------------------------------------------------------
__global__ void __launch_bounds__(128, 2)
gemm_kernel(float* __restrict__ out) {
    extern __shared__ char smem[];
    const uint32_t sb = smem_u32(smem);
    const int tid = threadIdx.x;
    const int l = tid & 31;
    const int w = tid >> 5;
    const int m0 = blockIdx.x * BM;

    // fragment mapping (identical to validated R3/R4 mapping)
    const int g = l >> 2, t4 = l & 3;
    const int wn = w * 48;
    const int rAf = (l & 7) + (((l >> 3) & 1) << 3);
    const int cAf = (l >> 4) * 16;
    const uint32_t aFragBase = (uint32_t)(rAf * STRIDE + cAf);
    const int rBf = (l & 7) + ((l >> 4) << 3);
    const int cBf = ((l >> 3) & 1) * 16;
    const uint32_t bFragBase = (uint32_t)((wn + rBf) * STRIDE + cBf);

    float acc[4][6][4];
#pragma unroll
    for (int mt = 0; mt < 4; mt++)
#pragma unroll
        for (int nt = 0; nt < 6; nt++)
#pragma unroll
            for (int c = 0; c < 4; c++) acc[mt][nt][c] = 0.0f;

    // cp.async mappings: A 256 16B-chunks (2/thread), B 768 (6/thread)
    const int arow0 = tid >> 2,        aj0 = tid & 3;          // chunk tid
    const int arow1 = (tid + 128) >> 2, aj1 = tid & 3;         // chunk tid+128
    auto cp_tile = [&](int kt) {
        const int stg = kt & 3;
        const uint32_t as = sb + stg * A_STAGE;
        const uint32_t bs = sb + SMEM_B0 + stg * B_STAGE;
        const __half* ah = g_h16 + (size_t)(m0)*CIN + kt * BK;
        cp_async16(as + arow0 * STRIDE + aj0 * 16, ah + (size_t)arow0 * CIN + aj0 * 8);
        cp_async16(as + arow1 * STRIDE + aj1 * 16, ah + (size_t)arow1 * CIN + aj1 * 8);
        const __half* bh = g_W16 + kt * BK;
#pragma unroll
        for (int i = 0; i < 6; i++) {
            const int c = tid + 128 * i;
            const int row = c >> 2, j = c & 3;
            cp_async16(bs + row * STRIDE + j * 16, bh + (size_t)row * CIN + j * 8);
        }
    };

    // prologue: 3 tiles in flight
    cp_tile(0); cp_commit();
    cp_tile(1); cp_commit();
    cp_tile(2); cp_commit();

#pragma unroll 1
    for (int kt = 0; kt < NKT; kt++) {
        if (kt + 3 < NKT) cp_tile(kt + 3);
        cp_commit();
        cp_wait3();
        __syncthreads();

        const uint32_t sA = sb + (kt & 3) * A_STAGE;
        const uint32_t sB = sb + SMEM_B0 + (kt & 3) * B_STAGE;
#pragma unroll
        for (int s = 0; s < 2; s++) {
            uint32_t af[4][4], bf[3][4];
#pragma unroll
            for (int mt = 0; mt < 4; mt++)
                ldsm_x4(af[mt], sA + aFragBase + mt * 16 * STRIDE + s * 32);
#pragma unroll
            for (int p = 0; p < 3; p++)
                ldsm_x4(bf[p], sB + bFragBase + p * 16 * STRIDE + s * 32);
#pragma unroll
            for (int mt = 0; mt < 4; mt++)
#pragma unroll
                for (int p = 0; p < 3; p++) {
                    mma16816(acc[mt][2 * p][0], acc[mt][2 * p][1],
                             acc[mt][2 * p][2], acc[mt][2 * p][3],
                             af[mt][0], af[mt][1], af[mt][2], af[mt][3],
                             bf[p][0], bf[p][1]);
                    mma16816(acc[mt][2 * p + 1][0], acc[mt][2 * p + 1][1],
                             acc[mt][2 * p + 1][2], acc[mt][2 * p + 1][3],
                             af[mt][0], af[mt][1], af[mt][2], af[mt][3],
                             bf[p][2], bf[p][3]);
                }
        }
        __syncthreads();
    }

    // epilogue
#pragma unroll
    for (int mt = 0; mt < 4; mt++) {
#pragma unroll
        for (int h = 0; h < 2; h++) {
            const int m = m0 + mt * 16 + g + 8 * h;
            const int b = m / HWSZ, hw = m - b * HWSZ;
            float* op = out + (size_t)b * (COUT * HWSZ) + hw;
#pragma unroll
            for (int nt = 0; nt < 6; nt++) {
                const int n = wn + nt * 8 + 2 * t4;
                op[(size_t)n * HWSZ]       = acc[mt][nt][2 * h + 0];
                op[(size_t)(n + 1) * HWSZ] = acc[mt][nt][2 * h + 1];
            }
        }
    }
}

// ---------------------------------------------------------------------------
extern "C" void kernel_launch(void* const* d_in, const int* in_sizes, int n_in,
                              void* d_out, int out_size) {
    (void)in_sizes; (void)n_in; (void)out_size;
    const float* x     = (const float*)d_in[0];
    const float* gamma = (const float*)d_in[1];
    const float* beta  = (const float*)d_in[2];
    const float* rmean = (const float*)d_in[3];
    const float* rvar  = (const float*)d_in[4];
    const float* W     = (const float*)d_in[5];
    float* out = (float*)d_out;

    cudaFuncSetAttribute(gemm_kernel, cudaFuncAttributeMaxDynamicSharedMemorySize, SMEM_TOTAL);

    fuse_kernel<<<NT_CTA + NW_CTA, 256>>>(x, gamma, beta, rmean, rvar, W);
    gemm_kernel<<<GRID_M, 128, SMEM_TOTAL>>>(out);
}